// round 4
// baseline (speedup 1.0000x reference)
#include <cuda_runtime.h>

#define BDIM 128
#define HDIM 32
#define SDIM 64
#define DDIM 128
#define STARTLEN 32
#define NT 256
#define BSTR (HDIM * SDIM * DDIM)

// SMEM (floats), total 19200 floats = 76800 B -> 3 CTAs/SM (225 KB/SM)
#define KS  0                         // [2][64][128] K cache
#define XS  16384                     // [2][128] x
#define QS  16640                     // [2][128] q (scale folded)
#define AO  16896                     // [2][128] attn out; att[2][64] overlays first 128
#define RED 17152                     // [16][128] partials; AOP overlays rows 0-7
#define SMEM_FLOATS 19200

typedef unsigned long long u64;

__device__ __forceinline__ void fma2(u64& acc, u64 a, u64 b) {
    asm("fma.rn.f32x2 %0, %1, %2, %0;" : "+l"(acc) : "l"(a), "l"(b));
}
__device__ __forceinline__ u64 pk2(float a, float b) {
    u64 r; asm("mov.b64 %0, {%1, %2};" : "=l"(r) : "f"(a), "f"(b)); return r;
}
__device__ __forceinline__ void upk2(float& lo, float& hi, u64 v) {
    asm("mov.b64 {%0, %1}, %2;" : "=f"(lo), "=f"(hi) : "l"(v));
}

__global__ void __launch_bounds__(NT, 3)
attn_decode_kernel(const float* __restrict__ x_in,
                   const float* __restrict__ k_in,
                   const float* __restrict__ v_in,
                   const float* __restrict__ wq,
                   const float* __restrict__ wk,
                   const float* __restrict__ wv,
                   const float* __restrict__ wo,
                   float* k_out, float* v_out, float* __restrict__ x_out)
{
    extern __shared__ float sm[];

    const int t = threadIdx.x;
    const int w = t >> 5;
    const int l = t & 31;
    const int h  = blockIdx.x >> 6;
    const int b0 = (blockIdx.x & 63) << 1;

    float* kg = k_out + (size_t)(b0 * HDIM + h) * (SDIM * DDIM);
    float* vg = v_out + (size_t)(b0 * HDIM + h) * (SDIM * DDIM);

    // ---- prologue: k_in -> (Ks smem + k_out), v_in -> v_out, x -> xs ----
    for (int b = 0; b < 2; ++b) {
        const float4* kin = (const float4*)(k_in + (size_t)((b0 + b) * HDIM + h) * (SDIM * DDIM));
        const float4* vin = (const float4*)(v_in + (size_t)((b0 + b) * HDIM + h) * (SDIM * DDIM));
        float4* kd = (float4*)(kg + (size_t)b * BSTR);
        float4* vd = (float4*)(vg + (size_t)b * BSTR);
        for (int i = t; i < SDIM * DDIM / 4; i += NT) {
            float4 kv = kin[i];
            *(float4*)&sm[KS + b * 8192 + 4 * i] = kv;
            kd[i] = kv;
            vd[i] = vin[i];
        }
        const float* xin = x_in + (size_t)((b0 + b) * HDIM + h) * DDIM;
        for (int d = t; d < DDIM; d += NT) sm[XS + b * DDIM + d] = xin[d];
    }
    __syncthreads();

    const u64* Wq2 = (const u64*)(wq + (size_t)h * DDIM * DDIM);
    const u64* Wk2 = (const u64*)(wk + (size_t)h * DDIM * DDIM);
    const u64* Wv2 = (const u64*)(wv + (size_t)h * DDIM * DDIM);
    const u64* Wo2 = (const u64*)(wo + (size_t)h * DDIM * DDIM);

    // P1 split: w0,w1 -> Wq d-halves; w2,w3 -> Wk d-halves; w4-7 -> Wv d-quarters
    const u64* Wp;
    int p_d0, p_nd;
    if (w < 2)      { Wp = Wq2; p_d0 = (w & 1) << 6;       p_nd = 64; }
    else if (w < 4) { Wp = Wk2; p_d0 = (w & 1) << 6;       p_nd = 64; }
    else            { Wp = Wv2; p_d0 = (w & 3) << 5;       p_nd = 32; }

    const int p2b = w >> 2, p2q = w & 3;     // P2/P4 task: (batch, s-quarter)

    for (int gen = STARTLEN; gen < SDIM; ++gen) {
        // ===== P1: QKV projections, 8 warps, packed f32x2 over e-pairs =====
        {
            u64 a0lo = 0, a0hi = 0, a1lo = 0, a1hi = 0;   // (batch, e-pair)
            const u64* wp = Wp + (size_t)p_d0 * 64 + 2 * l;
            #pragma unroll 8
            for (int dd = 0; dd < p_nd; ++dd) {
                int d = p_d0 + dd;
                u64 w01 = wp[0], w23 = wp[1];             // one LDG.128 worth
                wp += 64;
                float x0 = sm[XS + d], x1 = sm[XS + DDIM + d];
                u64 p0 = pk2(x0, x0), p1 = pk2(x1, x1);
                fma2(a0lo, w01, p0); fma2(a0hi, w23, p0);
                fma2(a1lo, w01, p1); fma2(a1hi, w23, p1);
            }
            float e0, e1, e2, e3;
            upk2(e0, e1, a0lo); upk2(e2, e3, a0hi);
            *(float4*)&sm[RED + ((w << 1) + 0) * DDIM + (l << 2)] = make_float4(e0, e1, e2, e3);
            upk2(e0, e1, a1lo); upk2(e2, e3, a1hi);
            *(float4*)&sm[RED + ((w << 1) + 1) * DDIM + (l << 2)] = make_float4(e0, e1, e2, e3);
        }
        __syncthreads();

        // ===== reduce partials -> qs, Ks[gen]+k_out, v_out =====
        {
            const int b = t >> 7, e = t & 127;
            // q: pslots 0,1
            float qv = sm[RED + ((0 << 1) + b) * DDIM + e] + sm[RED + ((1 << 1) + b) * DDIM + e];
            sm[QS + b * DDIM + e] = qv * 0.125f;
            // k: pslots 2,3
            float kv = sm[RED + ((2 << 1) + b) * DDIM + e] + sm[RED + ((3 << 1) + b) * DDIM + e];
            sm[KS + (b * SDIM + gen) * DDIM + e] = kv;
            __stcs(&kg[(size_t)b * BSTR + gen * DDIM + e], kv);
            // v: pslots 4-7
            float vv = sm[RED + ((4 << 1) + b) * DDIM + e] + sm[RED + ((5 << 1) + b) * DDIM + e]
                     + sm[RED + ((6 << 1) + b) * DDIM + e] + sm[RED + ((7 << 1) + b) * DDIM + e];
            vg[(size_t)b * BSTR + gen * DDIM + e] = vv;
        }
        __syncthreads();

        // ===== P2: QK scores, warp=(batch, s-quarter), f32x2 dot =====
        {
            float4 q4 = *(const float4*)&sm[QS + p2b * DDIM + (l << 2)];
            u64 q01 = pk2(q4.x, q4.y), q23 = pk2(q4.z, q4.w);
            const u64* kb2 = (const u64*)&sm[KS + p2b * SDIM * DDIM];
            #pragma unroll 4
            for (int r = 0; r < 16; ++r) {
                int s = (p2q << 4) + r;
                u64 pr = 0;
                fma2(pr, kb2[s * 64 + 2 * l], q01);
                fma2(pr, kb2[s * 64 + 2 * l + 1], q23);
                float plo, phi; upk2(plo, phi, pr);
                float p = plo + phi;
                #pragma unroll
                for (int o = 16; o > 0; o >>= 1) p += __shfl_xor_sync(0xFFFFFFFFu, p, o);
                if (l == 0) sm[AO + p2b * SDIM + s] = p;    // att overlays AO
            }
        }
        __syncthreads();

        // ===== P3: softmax, warps 0,1 =====
        if (w < 2) {
            float s0 = sm[AO + w * SDIM + l];
            float s1 = sm[AO + w * SDIM + 32 + l];
            float mx = fmaxf(s0, s1);
            #pragma unroll
            for (int o = 16; o > 0; o >>= 1) mx = fmaxf(mx, __shfl_xor_sync(0xFFFFFFFFu, mx, o));
            float e0 = __expf(s0 - mx);
            float e1 = __expf(s1 - mx);
            float su = e0 + e1;
            #pragma unroll
            for (int o = 16; o > 0; o >>= 1) su += __shfl_xor_sync(0xFFFFFFFFu, su, o);
            float inv = 1.0f / su;
            sm[AO + w * SDIM + l]      = e0 * inv;
            sm[AO + w * SDIM + 32 + l] = e1 * inv;
        }
        __syncthreads();

        // ===== P4: AV partials, warp=(batch, s-quarter), V from L2, f32x2 =====
        {
            u64 c01 = 0, c23 = 0;
            const u64* vb2 = (const u64*)(vg + (size_t)p2b * BSTR);
            #pragma unroll 8
            for (int i = 0; i < 16; ++i) {
                int s = (p2q << 4) + i;
                u64 v01 = vb2[s * 64 + 2 * l];
                u64 v23 = vb2[s * 64 + 2 * l + 1];
                float a = sm[AO + p2b * SDIM + s];
                u64 pa = pk2(a, a);
                fma2(c01, v01, pa); fma2(c23, v23, pa);
            }
            float e0, e1, e2, e3;
            upk2(e0, e1, c01); upk2(e2, e3, c23);
            *(float4*)&sm[RED + w * DDIM + (l << 2)] = make_float4(e0, e1, e2, e3);  // AOP rows 0-7
        }
        __syncthreads();

        // ===== AOP reduce -> ao (overwrites att; safe post-barrier) =====
        {
            const int b = t >> 7, e = t & 127;
            float v = sm[RED + ((b << 2) + 0) * DDIM + e] + sm[RED + ((b << 2) + 1) * DDIM + e]
                    + sm[RED + ((b << 2) + 2) * DDIM + e] + sm[RED + ((b << 2) + 3) * DDIM + e];
            sm[AO + b * DDIM + e] = v;
        }
        __syncthreads();

        // ===== P5: O projection, warp = d-eighth, weight loaded once, f32x2 =====
        {
            u64 a0lo = 0, a0hi = 0, a1lo = 0, a1hi = 0;
            const int d0 = w << 4;
            const u64* wp = Wo2 + (size_t)d0 * 64 + 2 * l;
            #pragma unroll 8
            for (int dd = 0; dd < 16; ++dd) {
                int d = d0 + dd;
                u64 w01 = wp[0], w23 = wp[1];
                wp += 64;
                float x0 = sm[AO + d], x1 = sm[AO + DDIM + d];
                u64 p0 = pk2(x0, x0), p1 = pk2(x1, x1);
                fma2(a0lo, w01, p0); fma2(a0hi, w23, p0);
                fma2(a1lo, w01, p1); fma2(a1hi, w23, p1);
            }
            float e0, e1, e2, e3;
            upk2(e0, e1, a0lo); upk2(e2, e3, a0hi);
            *(float4*)&sm[RED + ((w << 1) + 0) * DDIM + (l << 2)] = make_float4(e0, e1, e2, e3);
            upk2(e0, e1, a1lo); upk2(e2, e3, a1hi);
            *(float4*)&sm[RED + ((w << 1) + 1) * DDIM + (l << 2)] = make_float4(e0, e1, e2, e3);
        }
        __syncthreads();

        // ===== x reduce: sum 8 d-eighth partials -> xs =====
        {
            const int b = t >> 7, e = t & 127;
            float v = 0.f;
            #pragma unroll
            for (int ss = 0; ss < 8; ++ss)
                v += sm[RED + ((ss << 1) + b) * DDIM + e];
            sm[XS + b * DDIM + e] = v;
        }
        __syncthreads();
    }

    // ---- epilogue: x only (k/v written through) ----
    {
        const int b = t >> 7, e = t & 127;
        x_out[(size_t)((b0 + b) * HDIM + h) * DDIM + e] = sm[XS + b * DDIM + e];
    }
}

extern "C" void kernel_launch(void* const* d_in, const int* in_sizes, int n_in,
                              void* d_out, int out_size)
{
    const float* x  = (const float*)d_in[0];
    const float* k  = (const float*)d_in[1];
    const float* v  = (const float*)d_in[2];
    const float* wq = (const float*)d_in[3];
    const float* wk = (const float*)d_in[4];
    const float* wv = (const float*)d_in[5];
    const float* wo = (const float*)d_in[6];

    float* out   = (float*)d_out;
    float* k_out = out;
    float* v_out = out + (size_t)BDIM * HDIM * SDIM * DDIM;
    float* x_out = out + (size_t)2 * BDIM * HDIM * SDIM * DDIM;

    size_t smem = SMEM_FLOATS * sizeof(float);
    cudaFuncSetAttribute(attn_decode_kernel,
                         cudaFuncAttributeMaxDynamicSharedMemorySize, (int)smem);

    attn_decode_kernel<<<BDIM * HDIM / 2, NT, smem>>>(
        x, k, v, wq, wk, wv, wo, k_out, v_out, x_out);
}

// round 5
// speedup vs baseline: 1.1321x; 1.1321x over previous
#include <cuda_runtime.h>

#define BDIM 128
#define HDIM 32
#define SDIM 64
#define DDIM 128
#define STARTLEN 32
#define NT 256
#define BSTR (HDIM * SDIM * DDIM)

// SMEM (floats): Ks[2][64][128]=16384, cur[2][128]=256, qs[2][128]=256,
// att[2][64]=128, red[16][128]=2048  -> 19072 floats = 76288 B -> 3 CTAs/SM
#define KS  0
#define CUR 16384
#define QS  16640
#define ATT 16896
#define RED 17024
#define SMEM_FLOATS 19072

// Combined weights Cm = Wo @ Wm, per head: [m][h][128][128]
__device__ float g_comb[3 * HDIM * DDIM * DDIM];   // 6 MB device scratch

__global__ void __launch_bounds__(256)
fuse_weights_kernel(const float* __restrict__ wq, const float* __restrict__ wk,
                    const float* __restrict__ wv, const float* __restrict__ wo)
{
    extern __shared__ float Ws[];            // right matrix Wm [128][128]
    const int h = blockIdx.x / 3;
    const int m = blockIdx.x % 3;
    const int t = threadIdx.x;
    const float* Wm = ((m == 0) ? wq : ((m == 1) ? wk : wv)) + (size_t)h * DDIM * DDIM;
    const float* Wo = wo + (size_t)h * DDIM * DDIM;

    for (int i = t; i < DDIM * DDIM / 4; i += 256)
        ((float4*)Ws)[i] = ((const float4*)Wm)[i];
    __syncthreads();

    const int f  = t & 127;
    const int dp = t >> 7;
    float* dst = g_comb + (size_t)(m * HDIM + h) * DDIM * DDIM;
    for (int dr = 0; dr < DDIM; dr += 2) {
        int d = dr + dp;
        const float* wrow = Wo + d * DDIM;
        float acc = 0.f;
        #pragma unroll 8
        for (int e = 0; e < DDIM; ++e)
            acc += wrow[e] * Ws[e * DDIM + f];
        dst[d * DDIM + f] = acc;
    }
}

__global__ void __launch_bounds__(NT, 3)
attn_decode_kernel(const float* __restrict__ x_in,
                   const float* __restrict__ k_in,
                   const float* __restrict__ v_in,
                   const float* __restrict__ wq,
                   const float* __restrict__ wk,
                   const float* __restrict__ wv,
                   const float* __restrict__ wo,
                   float* k_out, float* v_out, float* __restrict__ x_out)
{
    extern __shared__ float sm[];

    const int t = threadIdx.x;
    const int w = t >> 5;
    const int l = t & 31;
    const int h  = blockIdx.x >> 6;
    const int b0 = (blockIdx.x & 63) << 1;

    float* kg = k_out + (size_t)(b0 * HDIM + h) * (SDIM * DDIM);
    float* vg = v_out + (size_t)(b0 * HDIM + h) * (SDIM * DDIM);

    // ---- prologue: K -> smem + k_out, V -> v_out, x -> cur ----
    for (int b = 0; b < 2; ++b) {
        const float4* kin = (const float4*)(k_in + (size_t)((b0 + b) * HDIM + h) * (SDIM * DDIM));
        const float4* vin = (const float4*)(v_in + (size_t)((b0 + b) * HDIM + h) * (SDIM * DDIM));
        float4* kd = (float4*)(kg + (size_t)b * BSTR);
        float4* vd = (float4*)(vg + (size_t)b * BSTR);
        for (int i = t; i < SDIM * DDIM / 4; i += NT) {
            float4 kv = kin[i];
            *(float4*)&sm[KS + b * 8192 + 4 * i] = kv;
            kd[i] = kv;
            vd[i] = vin[i];
        }
        const float* xin = x_in + (size_t)((b0 + b) * HDIM + h) * DDIM;
        for (int d = t; d < DDIM; d += NT) sm[CUR + b * DDIM + d] = xin[d];
    }
    __syncthreads();

    // original weights (first step) and combined weights (steady state)
    const float4* Wq4 = (const float4*)(wq + (size_t)h * DDIM * DDIM);
    const float4* Wk4 = (const float4*)(wk + (size_t)h * DDIM * DDIM);
    const float4* Wv4 = (const float4*)(wv + (size_t)h * DDIM * DDIM);
    const float4* Wo4 = (const float4*)(wo + (size_t)h * DDIM * DDIM);
    const float4* Cq4 = (const float4*)(g_comb + (size_t)(0 * HDIM + h) * DDIM * DDIM);
    const float4* Ck4 = (const float4*)(g_comb + (size_t)(1 * HDIM + h) * DDIM * DDIM);
    const float4* Cv4 = (const float4*)(g_comb + (size_t)(2 * HDIM + h) * DDIM * DDIM);

    // P1 split: w0,w1 -> q d-halves; w2,w3 -> k d-halves; w4-7 -> v d-quarters
    int p_d0, p_nd, p_m;
    if (w < 2)      { p_m = 0; p_d0 = (w & 1) << 6; p_nd = 64; }
    else if (w < 4) { p_m = 1; p_d0 = (w & 1) << 6; p_nd = 64; }
    else            { p_m = 2; p_d0 = (w & 3) << 5; p_nd = 32; }
    const float4* WpO = (p_m == 0) ? Wq4 : ((p_m == 1) ? Wk4 : Wv4);
    const float4* WpC = (p_m == 0) ? Cq4 : ((p_m == 1) ? Ck4 : Cv4);

    for (int gen = STARTLEN; gen < SDIM; ++gen) {
        // ===== P1: QKV projections from cur (x on first step, ao afterwards) =====
        {
            const float4* Wp = (gen == STARTLEN) ? WpO : WpC;
            float4 a0 = {0,0,0,0}, a1 = {0,0,0,0};
            #pragma unroll 8
            for (int dd = 0; dd < p_nd; ++dd) {
                int d = p_d0 + dd;
                float4 wv4 = Wp[d * 32 + l];                  // LDG.128, L2/L1
                float x0 = sm[CUR + d];
                float x1 = sm[CUR + DDIM + d];
                a0.x += x0 * wv4.x; a0.y += x0 * wv4.y; a0.z += x0 * wv4.z; a0.w += x0 * wv4.w;
                a1.x += x1 * wv4.x; a1.y += x1 * wv4.y; a1.z += x1 * wv4.z; a1.w += x1 * wv4.w;
            }
            *(float4*)&sm[RED + ((w << 1) + 0) * DDIM + (l << 2)] = a0;
            *(float4*)&sm[RED + ((w << 1) + 1) * DDIM + (l << 2)] = a1;
        }
        __syncthreads();

        // ===== reduce partials -> qs (scaled), Ks[gen]+k_out, v_out =====
        {
            const int b = t >> 7, e = t & 127;
            float qv = sm[RED + (0 + b) * DDIM + e] + sm[RED + (2 + b) * DDIM + e];
            sm[QS + b * DDIM + e] = qv * 0.125f;
            float kv = sm[RED + (4 + b) * DDIM + e] + sm[RED + (6 + b) * DDIM + e];
            sm[KS + (b * SDIM + gen) * DDIM + e] = kv;
            kg[(size_t)b * BSTR + gen * DDIM + e] = kv;
            float vv = sm[RED + (8 + b) * DDIM + e] + sm[RED + (10 + b) * DDIM + e]
                     + sm[RED + (12 + b) * DDIM + e] + sm[RED + (14 + b) * DDIM + e];
            vg[(size_t)b * BSTR + gen * DDIM + e] = vv;
        }
        __syncthreads();

        // ===== P2: QK scores, warp=(batch, s-quarter), lanes over d =====
        {
            const int bb = w >> 2;
            const int s0 = (w & 3) << 4;
            float4 q4 = *(const float4*)&sm[QS + bb * DDIM + (l << 2)];
            #pragma unroll 4
            for (int r = 0; r < 16; ++r) {
                int s = s0 + r;
                float4 k4 = *(const float4*)&sm[KS + (bb * SDIM + s) * DDIM + (l << 2)];
                float p = k4.x * q4.x + k4.y * q4.y + k4.z * q4.z + k4.w * q4.w;
                #pragma unroll
                for (int o = 16; o > 0; o >>= 1) p += __shfl_xor_sync(0xFFFFFFFFu, p, o);
                if (l == 0) sm[ATT + bb * SDIM + s] = p;
            }
        }
        __syncthreads();

        // ===== P3: softmax, warps 0,1 =====
        if (w < 2) {
            float s0v = sm[ATT + w * SDIM + l];
            float s1v = sm[ATT + w * SDIM + 32 + l];
            float mx = fmaxf(s0v, s1v);
            #pragma unroll
            for (int o = 16; o > 0; o >>= 1) mx = fmaxf(mx, __shfl_xor_sync(0xFFFFFFFFu, mx, o));
            float e0 = __expf(s0v - mx);
            float e1 = __expf(s1v - mx);
            float su = e0 + e1;
            #pragma unroll
            for (int o = 16; o > 0; o >>= 1) su += __shfl_xor_sync(0xFFFFFFFFu, su, o);
            float inv = 1.0f / su;
            sm[ATT + w * SDIM + l]      = e0 * inv;
            sm[ATT + w * SDIM + 32 + l] = e1 * inv;
        }
        __syncthreads();

        // ===== P4: AV (V from L2), result straight into cur (next step input) =====
        {
            const int b = t >> 7, d = t & 127;
            const float* vb = vg + (size_t)b * BSTR + d;
            const float* ab = sm + ATT + b * SDIM;
            float acc = 0.f;
            #pragma unroll 8
            for (int s = 0; s < SDIM; ++s) acc += ab[s] * vb[s * DDIM];
            sm[CUR + b * DDIM + d] = acc;
        }
        __syncthreads();
    }

    // ---- epilogue: x_out = cur @ Wo (done once) ----
    {
        float4 a0 = {0,0,0,0}, a1 = {0,0,0,0};
        const int d0 = w << 4;
        #pragma unroll 8
        for (int dd = 0; dd < 16; ++dd) {
            int d = d0 + dd;
            float4 wv4 = Wo4[d * 32 + l];
            float x0 = sm[CUR + d];
            float x1 = sm[CUR + DDIM + d];
            a0.x += x0 * wv4.x; a0.y += x0 * wv4.y; a0.z += x0 * wv4.z; a0.w += x0 * wv4.w;
            a1.x += x1 * wv4.x; a1.y += x1 * wv4.y; a1.z += x1 * wv4.z; a1.w += x1 * wv4.w;
        }
        *(float4*)&sm[RED + ((w << 1) + 0) * DDIM + (l << 2)] = a0;
        *(float4*)&sm[RED + ((w << 1) + 1) * DDIM + (l << 2)] = a1;
    }
    __syncthreads();
    {
        const int b = t >> 7, e = t & 127;
        float v = 0.f;
        #pragma unroll
        for (int ww = 0; ww < 8; ++ww)
            v += sm[RED + ((ww << 1) + b) * DDIM + e];
        x_out[(size_t)((b0 + b) * HDIM + h) * DDIM + e] = v;
    }
}

extern "C" void kernel_launch(void* const* d_in, const int* in_sizes, int n_in,
                              void* d_out, int out_size)
{
    const float* x  = (const float*)d_in[0];
    const float* k  = (const float*)d_in[1];
    const float* v  = (const float*)d_in[2];
    const float* wq = (const float*)d_in[3];
    const float* wk = (const float*)d_in[4];
    const float* wv = (const float*)d_in[5];
    const float* wo = (const float*)d_in[6];

    float* out   = (float*)d_out;
    float* k_out = out;
    float* v_out = out + (size_t)BDIM * HDIM * SDIM * DDIM;
    float* x_out = out + (size_t)2 * BDIM * HDIM * SDIM * DDIM;

    // pre-kernel: combined weights Cm = Wo @ Wm (graph-capturable, no allocs)
    size_t fuse_smem = DDIM * DDIM * sizeof(float);   // 64 KB
    cudaFuncSetAttribute(fuse_weights_kernel,
                         cudaFuncAttributeMaxDynamicSharedMemorySize, (int)fuse_smem);
    fuse_weights_kernel<<<HDIM * 3, 256, fuse_smem>>>(wq, wk, wv, wo);

    size_t smem = SMEM_FLOATS * sizeof(float);
    cudaFuncSetAttribute(attn_decode_kernel,
                         cudaFuncAttributeMaxDynamicSharedMemorySize, (int)smem);
    attn_decode_kernel<<<BDIM * HDIM / 2, NT, smem>>>(
        x, k, v, wq, wk, wv, wo, k_out, v_out, x_out);
}

// round 6
// speedup vs baseline: 1.3746x; 1.2143x over previous
#include <cuda_runtime.h>

#define BDIM 128
#define HDIM 32
#define SDIM 64
#define DDIM 128
#define STARTLEN 32
#define NT 256
#define BSTR (HDIM * SDIM * DDIM)

// SMEM (floats): Ks[2][64][128]=16384, cur[2][128]=256, red[20][128]=2560
// q overlays RED rows 0-1; att overlays RED rows 2-3.  Total 19200 fl = 76800 B -> 3 CTAs/SM
#define KS   0
#define CUR  16384
#define RED  16640
#define ATTB (RED + 2 * DDIM)
#define SMEM_FLOATS 19200

// Fused weights per head, concatenated: [h][384][128] (rows 0-127=Wo@Wq, 128-255=Wo@Wk, 256-383=Wo@Wv)
__device__ float g_comb[HDIM * 3 * DDIM * DDIM];   // 6 MB scratch

// ---------------- fast fuse kernel: C = Wo @ Wm, register-tiled ----------------
__global__ void __launch_bounds__(256)
fuse_weights_kernel(const float* __restrict__ wq, const float* __restrict__ wk,
                    const float* __restrict__ wv, const float* __restrict__ wo)
{
    __shared__ float Ws[DDIM * DDIM];       // Wm  (64 KB)
    __shared__ float Wop[64 * DDIM];        // Wo row panel (32 KB)
    const int h    = blockIdx.x / 6;
    const int rem  = blockIdx.x % 6;
    const int m    = rem >> 1;
    const int d0   = (rem & 1) << 6;        // 64-row panel
    const int t    = threadIdx.x;

    const float* Wm = ((m == 0) ? wq : ((m == 1) ? wk : wv)) + (size_t)h * DDIM * DDIM;
    const float* Wo = wo + (size_t)h * DDIM * DDIM;

    for (int i = t; i < DDIM * DDIM / 4; i += 256)
        ((float4*)Ws)[i] = ((const float4*)Wm)[i];
    for (int i = t; i < 64 * DDIM / 4; i += 256)
        ((float4*)Wop)[i] = ((const float4*)(Wo + d0 * DDIM))[i];
    __syncthreads();

    const int c = t & 15;                   // col group: f = c*8 .. c*8+7
    const int r = t >> 4;                   // row group: d = r*4 .. r*4+3 (panel-local)
    float acc[4][8];
    #pragma unroll
    for (int i = 0; i < 4; ++i)
        #pragma unroll
        for (int j = 0; j < 8; ++j) acc[i][j] = 0.f;

    #pragma unroll 4
    for (int e = 0; e < DDIM; ++e) {
        float4 wm0 = *(const float4*)&Ws[e * DDIM + c * 8];
        float4 wm1 = *(const float4*)&Ws[e * DDIM + c * 8 + 4];
        #pragma unroll
        for (int i = 0; i < 4; ++i) {
            float wo_v = Wop[(r * 4 + i) * DDIM + e];
            acc[i][0] += wo_v * wm0.x; acc[i][1] += wo_v * wm0.y;
            acc[i][2] += wo_v * wm0.z; acc[i][3] += wo_v * wm0.w;
            acc[i][4] += wo_v * wm1.x; acc[i][5] += wo_v * wm1.y;
            acc[i][6] += wo_v * wm1.z; acc[i][7] += wo_v * wm1.w;
        }
    }

    float* dst = g_comb + ((size_t)h * 384 + m * DDIM + d0) * DDIM;
    #pragma unroll
    for (int i = 0; i < 4; ++i) {
        *(float4*)&dst[(r * 4 + i) * DDIM + c * 8]     = make_float4(acc[i][0], acc[i][1], acc[i][2], acc[i][3]);
        *(float4*)&dst[(r * 4 + i) * DDIM + c * 8 + 4] = make_float4(acc[i][4], acc[i][5], acc[i][6], acc[i][7]);
    }
}

// ---------------- decode kernel ----------------
__global__ void __launch_bounds__(NT, 3)
attn_decode_kernel(const float* __restrict__ x_in,
                   const float* __restrict__ k_in,
                   const float* __restrict__ v_in,
                   const float* __restrict__ wq,
                   const float* __restrict__ wk,
                   const float* __restrict__ wv,
                   const float* __restrict__ wo,
                   float* k_out, float* v_out, float* __restrict__ x_out)
{
    extern __shared__ float sm[];

    const int t = threadIdx.x;
    const int w = t >> 5;
    const int l = t & 31;
    const int h  = blockIdx.x >> 6;
    const int b0 = (blockIdx.x & 63) << 1;

    float* kg = k_out + (size_t)(b0 * HDIM + h) * (SDIM * DDIM);
    float* vg = v_out + (size_t)(b0 * HDIM + h) * (SDIM * DDIM);

    // ---- prologue: K -> smem + k_out, V -> v_out, x -> cur ----
    for (int b = 0; b < 2; ++b) {
        const float4* kin = (const float4*)(k_in + (size_t)((b0 + b) * HDIM + h) * (SDIM * DDIM));
        const float4* vin = (const float4*)(v_in + (size_t)((b0 + b) * HDIM + h) * (SDIM * DDIM));
        float4* kd = (float4*)(kg + (size_t)b * BSTR);
        float4* vd = (float4*)(vg + (size_t)b * BSTR);
        for (int i = t; i < SDIM * DDIM / 4; i += NT) {
            float4 kv = kin[i];
            *(float4*)&sm[KS + b * 8192 + 4 * i] = kv;
            kd[i] = kv;
            vd[i] = vin[i];
        }
        const float* xin = x_in + (size_t)((b0 + b) * HDIM + h) * DDIM;
        for (int d = t; d < DDIM; d += NT) sm[CUR + b * DDIM + d] = xin[d];
    }
    __syncthreads();

    // P1 flat split: 384 rows (q|k|v), warp w -> rows [48w, 48w+48)
    const int r0  = w * 48;
    const int mA  = r0 >> 7;
    const int dA  = r0 & 127;                 // local start row in matrix mA
    const int nA  = min(48, 128 - dA);
    const int nB  = 48 - nA;                  // rows in matrix mA+1 (local start 0)
    const int extra = (w > 2) + (w > 5);
    const int slotA = w + extra;
    const int slotB = slotA + 1;

    const float* origM[3] = { wq + (size_t)h * DDIM * DDIM,
                              wk + (size_t)h * DDIM * DDIM,
                              wv + (size_t)h * DDIM * DDIM };
    const float* Ch = g_comb + (size_t)h * 384 * DDIM;

    const float4* origA4  = (const float4*)(origM[mA] + (size_t)dA * DDIM);
    const float4* fusedA4 = (const float4*)(Ch + (size_t)r0 * DDIM);
    const float4* origB4  = (nB > 0) ? (const float4*)origM[mA + 1] : nullptr;
    const float4* fusedB4 = (const float4*)(Ch + (size_t)(r0 + nA) * DDIM);

    const int p2b = w >> 2, p2s0 = (w & 3) << 4;     // P2 task: (batch, s-quarter)
    const int p4b = t >> 7, p4d = t & 127;           // P4 task: (batch, d)

    for (int gen = STARTLEN; gen < SDIM; ++gen) {
        const bool first = (gen == STARTLEN);

        // ===== P1: balanced projections (48 rows/warp, 2 batches) =====
        {
            const float4* Wp = first ? origA4 : fusedA4;
            float4 a0 = {0,0,0,0}, a1 = {0,0,0,0};
            #pragma unroll 8
            for (int i = 0; i < nA; ++i) {
                float4 wv4 = Wp[i * 32 + l];
                float x0 = sm[CUR + dA + i];
                float x1 = sm[CUR + DDIM + dA + i];
                a0.x += x0 * wv4.x; a0.y += x0 * wv4.y; a0.z += x0 * wv4.z; a0.w += x0 * wv4.w;
                a1.x += x1 * wv4.x; a1.y += x1 * wv4.y; a1.z += x1 * wv4.z; a1.w += x1 * wv4.w;
            }
            *(float4*)&sm[RED + (slotA * 2 + 0) * DDIM + (l << 2)] = a0;
            *(float4*)&sm[RED + (slotA * 2 + 1) * DDIM + (l << 2)] = a1;
            if (nB > 0) {
                const float4* Wp2 = first ? origB4 : fusedB4;
                float4 c0 = {0,0,0,0}, c1 = {0,0,0,0};
                #pragma unroll 8
                for (int i = 0; i < nB; ++i) {
                    float4 wv4 = Wp2[i * 32 + l];
                    float x0 = sm[CUR + i];
                    float x1 = sm[CUR + DDIM + i];
                    c0.x += x0 * wv4.x; c0.y += x0 * wv4.y; c0.z += x0 * wv4.z; c0.w += x0 * wv4.w;
                    c1.x += x1 * wv4.x; c1.y += x1 * wv4.y; c1.z += x1 * wv4.z; c1.w += x1 * wv4.w;
                }
                *(float4*)&sm[RED + (slotB * 2 + 0) * DDIM + (l << 2)] = c0;
                *(float4*)&sm[RED + (slotB * 2 + 1) * DDIM + (l << 2)] = c1;
            }
        }
        __syncthreads();

        // ===== reduce: q (slots 0-2) -> RED rows 0-1 (scaled); k (3-6) -> Ks+kg; v (7-9) -> vg =====
        {
            const int b = t >> 7, e = t & 127;
            float qv = sm[RED + (0 + b) * DDIM + e] + sm[RED + (2 + b) * DDIM + e]
                     + sm[RED + (4 + b) * DDIM + e];
            float kv = sm[RED + (6 + b) * DDIM + e] + sm[RED + (8 + b) * DDIM + e]
                     + sm[RED + (10 + b) * DDIM + e] + sm[RED + (12 + b) * DDIM + e];
            float vv = sm[RED + (14 + b) * DDIM + e] + sm[RED + (16 + b) * DDIM + e]
                     + sm[RED + (18 + b) * DDIM + e];
            sm[RED + b * DDIM + e] = qv * 0.125f;        // q overlays rows 0-1 (self-column only)
            sm[KS + (b * SDIM + gen) * DDIM + e] = kv;
            kg[(size_t)b * BSTR + gen * DDIM + e] = kv;
            vg[(size_t)b * BSTR + gen * DDIM + e] = vv;
        }
        __syncthreads();

        // ===== P2: QK scores -> raw att (RED rows 2-3) =====
        {
            float4 q4 = *(const float4*)&sm[RED + p2b * DDIM + (l << 2)];
            #pragma unroll 4
            for (int r = 0; r < 16; ++r) {
                int s = p2s0 + r;
                float4 k4 = *(const float4*)&sm[KS + (p2b * SDIM + s) * DDIM + (l << 2)];
                float p = k4.x * q4.x + k4.y * q4.y + k4.z * q4.z + k4.w * q4.w;
                #pragma unroll
                for (int o = 16; o > 0; o >>= 1) p += __shfl_xor_sync(0xFFFFFFFFu, p, o);
                if (l == 0) sm[ATTB + p2b * SDIM + s] = p;
            }
        }
        __syncthreads();

        // ===== P4: per-warp softmax (registers) + AV -> cur =====
        {
            float s0 = sm[ATTB + p4b * SDIM + l];
            float s1 = sm[ATTB + p4b * SDIM + 32 + l];
            float mx = fmaxf(s0, s1);
            #pragma unroll
            for (int o = 16; o > 0; o >>= 1) mx = fmaxf(mx, __shfl_xor_sync(0xFFFFFFFFu, mx, o));
            float e0 = __expf(s0 - mx);
            float e1 = __expf(s1 - mx);
            float su = e0 + e1;
            #pragma unroll
            for (int o = 16; o > 0; o >>= 1) su += __shfl_xor_sync(0xFFFFFFFFu, su, o);
            float inv = 1.0f / su;
            float p0 = e0 * inv, p1 = e1 * inv;

            const float* vb = vg + (size_t)p4b * BSTR + p4d;
            float acc = 0.f;
            #pragma unroll 8
            for (int s = 0; s < 32; ++s) {
                float a = __shfl_sync(0xFFFFFFFFu, p0, s);
                acc += a * vb[s * DDIM];
            }
            #pragma unroll 8
            for (int s = 0; s < 32; ++s) {
                float a = __shfl_sync(0xFFFFFFFFu, p1, s);
                acc += a * vb[(32 + s) * DDIM];
            }
            sm[CUR + p4b * DDIM + p4d] = acc;
        }
        __syncthreads();
    }

    // ---- epilogue: x_out = cur @ Wo ----
    const float4* Wo4 = (const float4*)(wo + (size_t)h * DDIM * DDIM);
    {
        float4 a0 = {0,0,0,0}, a1 = {0,0,0,0};
        const int d0 = w << 4;
        #pragma unroll 8
        for (int dd = 0; dd < 16; ++dd) {
            int d = d0 + dd;
            float4 wv4 = Wo4[d * 32 + l];
            float x0 = sm[CUR + d];
            float x1 = sm[CUR + DDIM + d];
            a0.x += x0 * wv4.x; a0.y += x0 * wv4.y; a0.z += x0 * wv4.z; a0.w += x0 * wv4.w;
            a1.x += x1 * wv4.x; a1.y += x1 * wv4.y; a1.z += x1 * wv4.z; a1.w += x1 * wv4.w;
        }
        *(float4*)&sm[RED + ((w << 1) + 0) * DDIM + (l << 2)] = a0;
        *(float4*)&sm[RED + ((w << 1) + 1) * DDIM + (l << 2)] = a1;
    }
    __syncthreads();
    {
        const int b = t >> 7, e = t & 127;
        float v = 0.f;
        #pragma unroll
        for (int ww = 0; ww < 8; ++ww)
            v += sm[RED + ((ww << 1) + b) * DDIM + e];
        x_out[(size_t)((b0 + b) * HDIM + h) * DDIM + e] = v;
    }
}

extern "C" void kernel_launch(void* const* d_in, const int* in_sizes, int n_in,
                              void* d_out, int out_size)
{
    const float* x  = (const float*)d_in[0];
    const float* k  = (const float*)d_in[1];
    const float* v  = (const float*)d_in[2];
    const float* wq = (const float*)d_in[3];
    const float* wk = (const float*)d_in[4];
    const float* wv = (const float*)d_in[5];
    const float* wo = (const float*)d_in[6];

    float* out   = (float*)d_out;
    float* k_out = out;
    float* v_out = out + (size_t)BDIM * HDIM * SDIM * DDIM;
    float* x_out = out + (size_t)2 * BDIM * HDIM * SDIM * DDIM;

    fuse_weights_kernel<<<HDIM * 6, 256>>>(wq, wk, wv, wo);

    size_t smem = SMEM_FLOATS * sizeof(float);
    cudaFuncSetAttribute(attn_decode_kernel,
                         cudaFuncAttributeMaxDynamicSharedMemorySize, (int)smem);
    attn_decode_kernel<<<BDIM * HDIM / 2, NT, smem>>>(
        x, k, v, wq, wk, wv, wo, k_out, v_out, x_out);
}